// round 3
// baseline (speedup 1.0000x reference)
#include <cuda_runtime.h>
#include <cstdint>

// Problem constants (fixed by the dataset)
#define NB     2
#define N_SRC  131072
#define N_DST  131072
#define FDIM   64
#define EPS_F  1e-8f

// Scratch: per-destination weight sums (512 KB)
__device__ float g_norm[N_DST];

__global__ void zero_norm_kernel() {
    int i = blockIdx.x * blockDim.x + threadIdx.x;
    if (i < N_DST) g_norm[i] = 0.0f;
}

// edge_index is int32 on device (JAX downcasts int64 without x64 mode).
__global__ void compute_norm_kernel(const int* __restrict__ edge_index,
                                    const float* __restrict__ weights,
                                    int E) {
    int e = blockIdx.x * blockDim.x + threadIdx.x;
    if (e < E) {
        unsigned d = (unsigned)edge_index[E + e];   // dst row
        if (d < N_DST) atomicAdd(&g_norm[d], weights[e]);
    }
}

// Zero the poisoned output buffer. NB*N_DST*FDIM = 16.7M floats = 4.19M float4.
__global__ void __launch_bounds__(256)
zero_out_kernel(float4* __restrict__ out, int n4) {
    int i = blockIdx.x * blockDim.x + threadIdx.x;
    if (i < n4) out[i] = make_float4(0.f, 0.f, 0.f, 0.f);
}

// One warp per edge.
// Lane layout: b = lane>>4 (batch 0/1), f4 = lane&15 (float4 index into F=64).
// Each lane: load x[b, src, f4*4..+3] as float4, scale, vector atomicAdd
// (sm_90+ float4 overload -> RED.E.ADD.F32.128) into out[b, dst, f4*4..+3].
__global__ void __launch_bounds__(256)
scatter_kernel(const float* __restrict__ x,
               const int* __restrict__ edge_index,
               const float* __restrict__ weights,
               float* __restrict__ out,
               int E) {
    int gtid = blockIdx.x * blockDim.x + threadIdx.x;
    int e    = gtid >> 5;
    int lane = threadIdx.x & 31;
    if (e >= E) return;

    unsigned s = (unsigned)edge_index[e];        // src row
    unsigned d = (unsigned)edge_index[E + e];    // dst row
    if (s >= N_SRC || d >= N_DST) return;        // safety: never trap

    float w = weights[e] / (g_norm[d] + EPS_F);

    int b  = lane >> 4;
    int f4 = lane & 15;

    const float4* xrow = reinterpret_cast<const float4*>(
        x + ((size_t)b * N_SRC + (size_t)s) * FDIM);
    float4 v = xrow[f4];
    v.x *= w; v.y *= w; v.z *= w; v.w *= w;

    float4* orow = reinterpret_cast<float4*>(
        out + ((size_t)b * N_DST + (size_t)d) * FDIM);

    atomicAdd(orow + f4, v);   // vector reduction (no return)
}

extern "C" void kernel_launch(void* const* d_in, const int* in_sizes, int n_in,
                              void* d_out, int out_size) {
    const float* x          = (const float*)d_in[0];
    const int*   edge_index = (const int*)d_in[1];
    const float* weights    = (const float*)d_in[2];
    float*       out        = (float*)d_out;

    const int E = in_sizes[2];   // weights element count

    // 1) zero the norm scratch (every replay)
    zero_norm_kernel<<<(N_DST + 255) / 256, 256>>>();

    // 2) zero the (poisoned) output
    {
        int n4 = out_size / 4;
        zero_out_kernel<<<(n4 + 255) / 256, 256>>>((float4*)d_out, n4);
    }

    // 3) per-destination weight sums
    compute_norm_kernel<<<(E + 255) / 256, 256>>>(edge_index, weights, E);

    // 4) normalized scatter-add SpMM: one warp per edge
    {
        int warps_per_block = 256 / 32;
        int blocks = (E + warps_per_block - 1) / warps_per_block;
        scatter_kernel<<<blocks, 256>>>(x, edge_index, weights, out, E);
    }
}

// round 4
// speedup vs baseline: 1.4348x; 1.4348x over previous
#include <cuda_runtime.h>
#include <cstdint>

// Problem constants (fixed by the dataset)
#define NB     2
#define N_SRC  131072
#define N_DST  131072
#define FDIM   64
#define EPS_F  1e-8f
#define EPW    4        // edges per warp

// Scratch: per-destination weight sums (512 KB)
__device__ float g_norm[N_DST];

// Fused zero: output (n4 float4) + g_norm (N_DST/4 float4).
__global__ void __launch_bounds__(256)
zero_all_kernel(float4* __restrict__ out, int n4) {
    int i = blockIdx.x * blockDim.x + threadIdx.x;
    float4 z = make_float4(0.f, 0.f, 0.f, 0.f);
    if (i < n4) out[i] = z;
    if (i < N_DST / 4) reinterpret_cast<float4*>(g_norm)[i] = z;
}

// edge_index is int32 on device (JAX downcasts int64 without x64 mode).
__global__ void compute_norm_kernel(const int* __restrict__ edge_index,
                                    const float* __restrict__ weights,
                                    int E) {
    int e = blockIdx.x * blockDim.x + threadIdx.x;
    if (e < E) {
        unsigned d = (unsigned)edge_index[E + e];
        if (d < N_DST) atomicAdd(&g_norm[d], weights[e]);
    }
}

// 4 edges per warp, front-batched loads for MLP.
// Lane layout per edge: b = lane>>4 (batch 0/1), f4 = lane&15 (float4 in F=64).
__global__ void __launch_bounds__(256)
scatter_kernel(const float* __restrict__ x,
               const int* __restrict__ edge_index,
               const float* __restrict__ weights,
               float* __restrict__ out,
               int E) {
    int warp = (blockIdx.x * blockDim.x + threadIdx.x) >> 5;
    int lane = threadIdx.x & 31;
    int e0   = warp * EPW;
    if (e0 >= E) return;

    int b  = lane >> 4;
    int f4 = lane & 15;

    // Phase 1: indices (broadcast loads across the warp)
    int s[EPW], d[EPW];
#pragma unroll
    for (int i = 0; i < EPW; i++) {
        int e = e0 + i;
        if (e < E) {
            unsigned si = (unsigned)edge_index[e];
            unsigned di = (unsigned)edge_index[E + e];
            s[i] = (si < N_SRC && di < N_DST) ? (int)si : -1;
            d[i] = (int)di;
        } else {
            s[i] = -1;
        }
    }

    // Phase 2: weights + norms (independent loads, overlap)
    float w[EPW];
#pragma unroll
    for (int i = 0; i < EPW; i++) {
        if (s[i] >= 0)
            w[i] = weights[e0 + i] / (g_norm[d[i]] + EPS_F);
    }

    // Phase 3: gather x (4 independent LDG.128 in flight per thread)
    float4 v[EPW];
#pragma unroll
    for (int i = 0; i < EPW; i++) {
        if (s[i] >= 0) {
            const float4* xrow = reinterpret_cast<const float4*>(
                x + ((size_t)b * N_SRC + (size_t)s[i]) * FDIM);
            v[i] = xrow[f4];
        }
    }

    // Phase 4: scale + vector reduction into out
#pragma unroll
    for (int i = 0; i < EPW; i++) {
        if (s[i] >= 0) {
            float4 t = v[i];
            t.x *= w[i]; t.y *= w[i]; t.z *= w[i]; t.w *= w[i];
            float4* orow = reinterpret_cast<float4*>(
                out + ((size_t)b * N_DST + (size_t)d[i]) * FDIM);
            atomicAdd(orow + f4, t);   // RED.E.ADD.F32.128
        }
    }
}

extern "C" void kernel_launch(void* const* d_in, const int* in_sizes, int n_in,
                              void* d_out, int out_size) {
    const float* x          = (const float*)d_in[0];
    const int*   edge_index = (const int*)d_in[1];
    const float* weights    = (const float*)d_in[2];
    float*       out        = (float*)d_out;

    const int E = in_sizes[2];   // weights element count

    // 1) zero output + norm scratch (every replay; output is poisoned)
    {
        int n4 = out_size / 4;
        zero_all_kernel<<<(n4 + 255) / 256, 256>>>((float4*)d_out, n4);
    }

    // 2) per-destination weight sums
    compute_norm_kernel<<<(E + 255) / 256, 256>>>(edge_index, weights, E);

    // 3) normalized scatter-add SpMM: 4 edges per warp
    {
        int warps  = (E + EPW - 1) / EPW;
        int blocks = (warps * 32 + 255) / 256;
        scatter_kernel<<<blocks, 256>>>(x, edge_index, weights, out, E);
    }
}